// round 10
// baseline (speedup 1.0000x reference)
#include <cuda_runtime.h>
#include <cuda_fp16.h>
#include <cstdint>

// ---------------------------------------------------------------- dims
#define L_DIM 16384
#define P_DIM 512
#define NCHUNK 512
#define CLEN (L_DIM / NCHUNK)        // 32
#define KTOT 1024                    // complex concat: [Xr | Xi]
#define NKB (KTOT / 32)              // 32 k-blocks of 32 halves (64B)

// ---------------------------------------------------------------- scratch
__device__ float g_lbr[P_DIM], g_lbi[P_DIM];
__device__ float g_bcr[P_DIM], g_bci[P_DIM];
__device__ double g_Ar[P_DIM], g_Ai[P_DIM];
__device__ float g_cfr[NCHUNK * P_DIM], g_cfi[NCHUNK * P_DIM];
__device__ float g_cir[NCHUNK * P_DIM], g_cii[NCHUNK * P_DIM];
// A = [Xr | Xi] fp16 Dekker split planes, k-block-tiled + pre-swizzled:
//   half index = (kb*L + row)*32 + (c ^ ((row>>1)&3))*8 + pos,  kb=k>>5, c=(k>>3)&3, pos=k&7
__device__ __half g_ah[(size_t)L_DIM * KTOT];
__device__ __half g_al[(size_t)L_DIM * KTOT];
// B = [Vr | -Vi] split planes, same tiling over n: (kb*512 + n)*32 + swz
__device__ __half g_bh[P_DIM * KTOT];
__device__ __half g_bl[P_DIM * KTOT];

// ---------------------------------------------------------------- helpers
__device__ __forceinline__ uint32_t smem_u32(const void* p) {
    uint32_t a;
    asm("{ .reg .u64 t; cvta.to.shared.u64 t, %1; cvt.u32.u64 %0, t; }" : "=r"(a) : "l"(p));
    return a;
}
__device__ __forceinline__ void split_h(float x, __half& h, __half& l) {
    h = __float2half_rn(x);
    float r = x - __half2float(h);
    l = __float2half_rn(r);
}
__device__ __forceinline__ void ldsm4(uint32_t* r, uint32_t addr) {
    asm volatile("ldmatrix.sync.aligned.m8n8.x4.shared.b16 {%0,%1,%2,%3}, [%4];"
                 : "=r"(r[0]), "=r"(r[1]), "=r"(r[2]), "=r"(r[3]) : "r"(addr));
}
#define MMA16816(c, a, b)                                                        \
    asm volatile("mma.sync.aligned.m16n8k16.row.col.f32.f16.f16.f32 "            \
                 "{%0,%1,%2,%3}, {%4,%5,%6,%7}, {%8,%9}, {%0,%1,%2,%3};"         \
                 : "+f"((c)[0]), "+f"((c)[1]), "+f"((c)[2]), "+f"((c)[3])        \
                 : "r"((a)[0]), "r"((a)[1]), "r"((a)[2]), "r"((a)[3]),           \
                   "r"((b)[0]), "r"((b)[1]))

#define MBAR_INIT(a, n) asm volatile("mbarrier.init.shared.b64 [%0], %1;" :: "r"(a), "r"(n) : "memory")
#define MBAR_ARRIVE(a)  asm volatile("mbarrier.arrive.shared.b64 _, [%0];" :: "r"(a) : "memory")
#define MBAR_EXPECT_TX(a, n) asm volatile("mbarrier.arrive.expect_tx.shared.b64 _, [%0], %1;" :: "r"(a), "r"(n) : "memory")
#define MBAR_WAIT(a, ph) do {                                                      \
    uint32_t _m = (a); uint32_t _p = (ph); uint32_t _d;                            \
    asm volatile("{ .reg .pred p; mbarrier.try_wait.parity.acquire.cta.shared::cta.b64 p, [%1], %2; selp.b32 %0,1,0,p; }" \
        : "=r"(_d) : "r"(_m), "r"(_p) : "memory");                                 \
    if (!_d) {                                                                     \
        asm volatile("{ .reg .pred P1; WL_%=: mbarrier.try_wait.parity.acquire.cta.shared::cta.b64 P1, [%0], %1, 0x989680;\n\t" \
            "@P1 bra.uni WD_%=; bra.uni WL_%=; WD_%=: }" :: "r"(_m), "r"(_p) : "memory"); \
    } } while (0)
#define FENCE_ASYNC() asm volatile("fence.proxy.async.shared::cta;" ::: "memory")

__device__ __forceinline__ void bulk_g2s(uint32_t smem_dst, const void* gmem_src,
                                         uint32_t bytes, uint32_t mbar) {
    asm volatile("cp.async.bulk.shared::cluster.global.mbarrier::complete_tx::bytes "
                 "[%0], [%1], %2, [%3];"
                 :: "r"(smem_dst), "l"(gmem_src), "r"(bytes), "r"(mbar) : "memory");
}

// ---------------------------------------------------------------- prep
__global__ void prep_kernel(const float* __restrict__ Lambda,
                            const float* __restrict__ log_step,
                            const float* __restrict__ Vr,
                            const float* __restrict__ Vi) {
    int n = blockIdx.x;
    int nsw = (n >> 1) & 3;
    for (int k = threadIdx.x; k < KTOT; k += blockDim.x) {
        float v = (k < P_DIM) ? Vr[n * P_DIM + k] : -Vi[n * P_DIM + (k - P_DIM)];
        __half h, l; split_h(v, h, l);
        int kb = k >> 5;
        int c = ((k >> 3) & 3) ^ nsw;
        size_t idx = ((size_t)kb * P_DIM + n) * 32 + c * 8 + (k & 7);
        g_bh[idx] = h;
        g_bl[idx] = l;
    }
    if (threadIdx.x == 0) {
        int p = n;
        float lre = -expf(Lambda[2 * p + 0]);
        float lim =  Lambda[2 * p + 1];
        float s   =  expf(log_step[p]);
        float er  =  expf(lre * s);
        float lbr = er * cosf(lim * s);
        float lbi = er * sinf(lim * s);
        g_lbr[p] = lbr; g_lbi[p] = lbi;
        float den = lre * lre + lim * lim;
        float nr = lbr - 1.0f, ni = lbi;
        g_bcr[p] = (nr * lre + ni * lim) / den;
        g_bci[p] = (ni * lre - nr * lim) / den;
        double ar = 1.0, ai = 0.0, br = (double)lbr, bi = (double)lbi;
        int e = CLEN;
        while (e) {
            if (e & 1) { double t = ar * br - ai * bi; ai = ar * bi + ai * br; ar = t; }
            double t2 = br * br - bi * bi; bi = 2.0 * br * bi; br = t2;
            e >>= 1;
        }
        g_Ar[p] = ar; g_Ai[p] = ai;
    }
}

// ---------------------------------------------------------------- scans
// grid NCHUNK, block 256: each thread owns channels p0=2*tid, p0+1 (2x ILP).
__global__ void local_scan_kernel(const float* __restrict__ u) {
    int t = threadIdx.x;
    int c = blockIdx.x;
    int p0 = 2 * t;
    float lr0 = g_lbr[p0],   li0 = g_lbi[p0],   br0 = g_bcr[p0],   bi0 = g_bci[p0];
    float lr1 = g_lbr[p0+1], li1 = g_lbi[p0+1], br1 = g_bcr[p0+1], bi1 = g_bci[p0+1];
    float xr0 = 0.0f, xi0 = 0.0f, xr1 = 0.0f, xi1 = 0.0f;
    const float* up = u + (size_t)(c * CLEN) * P_DIM + p0;
#pragma unroll 4
    for (int i = 0; i < CLEN; i++) {
        float2 uv = *(const float2*)(up + (size_t)i * P_DIM);
        float nr0 = fmaf(lr0, xr0, fmaf(-li0, xi0, br0 * uv.x));
        float ni0 = fmaf(lr0, xi0, fmaf( li0, xr0, bi0 * uv.x));
        float nr1 = fmaf(lr1, xr1, fmaf(-li1, xi1, br1 * uv.y));
        float ni1 = fmaf(lr1, xi1, fmaf( li1, xr1, bi1 * uv.y));
        xr0 = nr0; xi0 = ni0; xr1 = nr1; xi1 = ni1;
    }
    g_cfr[c * P_DIM + p0] = xr0;     g_cfi[c * P_DIM + p0] = xi0;
    g_cfr[c * P_DIM + p0 + 1] = xr1; g_cfi[c * P_DIM + p0 + 1] = xi1;
}

// Shuffle-based log-depth inter-chunk carry scan (double precision).
// Block = 512 threads = NCHUNK chunks for channel p = blockIdx.x.
__global__ void carry_scan_kernel() {
    const int p = blockIdx.x;
    const int c = threadIdx.x;
    const int lane = c & 31;
    const int w = c >> 5;                 // 16 warps

    double vr = (double)g_cfr[c * P_DIM + p];
    double vi = (double)g_cfi[c * P_DIM + p];
    double qr = g_Ar[p], qi = g_Ai[p];    // A^(2^s), s=0

    double p2r[5], p2i[5];                // A^1..A^16
    int kidx = 0;
#pragma unroll
    for (int s = 1; s < 32; s <<= 1) {
        p2r[kidx] = qr; p2i[kidx] = qi; kidx++;
        double tr = __shfl_up_sync(0xffffffffu, vr, s);
        double ti = __shfl_up_sync(0xffffffffu, vi, s);
        if (lane >= s) {
            vr = fma(qr, tr, fma(-qi, ti, vr));
            vi = fma(qr, ti, fma( qi, tr, vi));
        }
        double nqr = qr * qr - qi * qi;
        qi = 2.0 * qr * qi;
        qr = nqr;                          // ends at A^32
    }

    __shared__ double swr[16], swi[16];
    if (lane == 31) { swr[w] = vr; swi[w] = vi; }
    __syncthreads();

    if (w == 0 && lane < 16) {             // scan 16 warp aggregates, mult A^32
        double xr = swr[lane], xi = swi[lane];
        double mr = qr, mi = qi;
#pragma unroll
        for (int s = 1; s < 16; s <<= 1) {
            double tr = __shfl_up_sync(0xffffu, xr, s);
            double ti = __shfl_up_sync(0xffffu, xi, s);
            if (lane >= s) {
                xr = fma(mr, tr, fma(-mi, ti, xr));
                xi = fma(mr, ti, fma( mi, tr, xi));
            }
            double nmr = mr * mr - mi * mi;
            mi = 2.0 * mr * mi;
            mr = nmr;
        }
        swr[lane] = xr; swi[lane] = xi;
    }
    __syncthreads();

    // exclusive local prefix within warp
    double er = __shfl_up_sync(0xffffffffu, vr, 1);
    double ei = __shfl_up_sync(0xffffffffu, vi, 1);
    if (lane == 0) { er = 0.0; ei = 0.0; }

    // compose with previous warps: + A^lane * Wagg[w-1]
    if (w > 0) {
        double plr = 1.0, pli = 0.0;
#pragma unroll
        for (int k = 0; k < 5; k++) {
            if ((lane >> k) & 1) {
                double t = plr * p2r[k] - pli * p2i[k];
                pli = plr * p2i[k] + pli * p2r[k];
                plr = t;
            }
        }
        double Wr = swr[w - 1], Wi = swi[w - 1];
        er = fma(plr, Wr, fma(-pli, Wi, er));
        ei = fma(plr, Wi, fma( pli, Wr, ei));
    }

    g_cir[c * P_DIM + p] = (float)er;
    g_cii[c * P_DIM + p] = (float)ei;
}

// Final scan writing A planes (tiled-swizzled). grid NCHUNK, 2 channels/thread,
// paired half2 stores (adjacent channels share kb/coff, consecutive pos).
__global__ void final_scan_kernel(const float* __restrict__ u) {
    int t = threadIdx.x;
    int c = blockIdx.x;
    int p0 = 2 * t;
    float lr0 = g_lbr[p0],   li0 = g_lbi[p0],   br0 = g_bcr[p0],   bi0 = g_bci[p0];
    float lr1 = g_lbr[p0+1], li1 = g_lbi[p0+1], br1 = g_bcr[p0+1], bi1 = g_bci[p0+1];
    float xr0 = g_cir[c * P_DIM + p0],     xi0 = g_cii[c * P_DIM + p0];
    float xr1 = g_cir[c * P_DIM + p0 + 1], xi1 = g_cii[c * P_DIM + p0 + 1];
    const float* up = u + (size_t)(c * CLEN) * P_DIM + p0;
    const size_t row0 = (size_t)(c * CLEN);
    const int kbr = p0 >> 5;                // Xr k-block
    const int kbi = (P_DIM >> 5) + kbr;     // Xi k-block
    const int coff = (p0 >> 3) & 3;         // same for p0+1 (p0 even)
    const int pos = p0 & 7;                 // even; p0+1 -> pos+1
#pragma unroll 4
    for (int i = 0; i < CLEN; i++) {
        float2 uv = *(const float2*)(up + (size_t)i * P_DIM);
        float nr0 = fmaf(lr0, xr0, fmaf(-li0, xi0, br0 * uv.x));
        float ni0 = fmaf(lr0, xi0, fmaf( li0, xr0, bi0 * uv.x));
        float nr1 = fmaf(lr1, xr1, fmaf(-li1, xi1, br1 * uv.y));
        float ni1 = fmaf(lr1, xi1, fmaf( li1, xr1, bi1 * uv.y));
        xr0 = nr0; xi0 = ni0; xr1 = nr1; xi1 = ni1;

        size_t row = row0 + i;
        int swz = (coff ^ ((int)(row >> 1) & 3)) * 8 + pos;
        size_t idxr = ((size_t)kbr * L_DIM + row) * 32 + swz;
        size_t idxi = ((size_t)kbi * L_DIM + row) * 32 + swz;

        __half h0, l0, h1, l1;
        split_h(xr0, h0, l0);
        split_h(xr1, h1, l1);
        *(__half2*)(g_ah + idxr) = __halves2half2(h0, h1);
        *(__half2*)(g_al + idxr) = __halves2half2(l0, l1);
        split_h(xi0, h0, l0);
        split_h(xi1, h1, l1);
        *(__half2*)(g_ah + idxi) = __halves2half2(h0, h1);
        *(__half2*)(g_al + idxi) = __halves2half2(l0, l1);
    }
}

// ---------------------------------------------------------------- GEMM (mma.sync f16 x3, bulk-DMA pipeline)
// 256x128 CTA tile, 8 warps 4(M) x 2(N), 64x64 per warp. 4-stage mbarrier pipe.
#define GBM 256
#define GBN 128
#define NS 4
#define NSTOT NKB                         // 32 stages of k32
#define A_PL 16384                        // 256 rows * 64B
#define B_PL 8192                         // 128 rows * 64B
#define STG (2 * A_PL + 2 * B_PL)         // 49152
#define OFF_AH 0
#define OFF_AL A_PL
#define OFF_BH (2 * A_PL)
#define OFF_BL (2 * A_PL + B_PL)
#define BAR_OFF (NS * STG)
#define GSMEM_TOTAL (NS * STG + 128)      // 196736

__global__ __launch_bounds__(256, 1)
void gemm_spike_mma(float* __restrict__ out) {
    extern __shared__ __align__(1024) char smem[];
    const uint32_t sbase = smem_u32(smem);
    const int tid = threadIdx.x;
    const int lane = tid & 31;
    const int wid = tid >> 5;
    const int warpM = wid & 3;
    const int warpN = wid >> 2;
    const int bm = blockIdx.y * GBM;
    const int bn = blockIdx.x * GBN;

    const uint32_t full0  = sbase + BAR_OFF;
    const uint32_t empty0 = sbase + BAR_OFF + 32;

    if (tid == 0) {
#pragma unroll
        for (int b = 0; b < NS; b++) {
            MBAR_INIT(full0 + b * 8, 1);
            MBAR_INIT(empty0 + b * 8, 256);
        }
    }
    __syncthreads();

    auto issue = [&](int si) {
        const uint32_t buf = sbase + (uint32_t)(si & (NS - 1)) * STG;
        MBAR_EXPECT_TX(full0 + (si & (NS - 1)) * 8, STG);
        const uint32_t mb = full0 + (si & (NS - 1)) * 8;
        bulk_g2s(buf + OFF_AH, g_ah + ((size_t)si * L_DIM + bm) * 32, A_PL, mb);
        bulk_g2s(buf + OFF_AL, g_al + ((size_t)si * L_DIM + bm) * 32, A_PL, mb);
        bulk_g2s(buf + OFF_BH, g_bh + ((size_t)si * P_DIM + bn) * 32, B_PL, mb);
        bulk_g2s(buf + OFF_BL, g_bl + ((size_t)si * P_DIM + bn) * 32, B_PL, mb);
    };

    if (tid == 0) {
        for (int si = 0; si < NS - 1; si++) issue(si);
    }

    float acc[4][8][4];
#pragma unroll
    for (int i = 0; i < 4; i++)
#pragma unroll
        for (int j = 0; j < 8; j++)
#pragma unroll
            for (int q = 0; q < 4; q++) acc[i][j][q] = 0.0f;

    const int a_r = warpM * 64 + (lane & 15);
    const int a_cbase = (lane >> 4);
    const int b_r = warpN * 64 + (lane & 7) + ((lane >> 4) << 3);
    const int b_cbase = (lane >> 3) & 1;

    for (int s = 0; s < NSTOT; s++) {
        const int b = s & (NS - 1);
        if (tid == 0) {
            int si = s + NS - 1;
            if (si < NSTOT) {
                int bb = si & (NS - 1);
                if (si >= NS) MBAR_WAIT(empty0 + bb * 8, ((si >> 2) - 1) & 1);
                issue(si);
            }
        }
        MBAR_WAIT(full0 + b * 8, (s >> 2) & 1);

        const uint32_t buf = sbase + (uint32_t)b * STG;
        const uint32_t sAh = buf + OFF_AH;
        const uint32_t sAl = buf + OFF_AL;
        const uint32_t sBh = buf + OFF_BH;
        const uint32_t sBl = buf + OFF_BL;

#pragma unroll
        for (int kk = 0; kk < 2; kk++) {
            uint32_t ah[4][4], al[4][4];
#pragma unroll
            for (int mt = 0; mt < 4; mt++) {
                int r = a_r + mt * 16;
                int c = kk * 2 + a_cbase;
                uint32_t off = (uint32_t)(r * 64 + ((c ^ ((r >> 1) & 3)) << 4));
                ldsm4(ah[mt], sAh + off);
                ldsm4(al[mt], sAl + off);
            }
            uint32_t bh[4][4], bl[4][4];
#pragma unroll
            for (int nh = 0; nh < 4; nh++) {
                int r = b_r + nh * 16;
                int c = kk * 2 + b_cbase;
                uint32_t off = (uint32_t)(r * 64 + ((c ^ ((r >> 1) & 3)) << 4));
                ldsm4(bh[nh], sBh + off);
                ldsm4(bl[nh], sBl + off);
            }
#pragma unroll
            for (int mt = 0; mt < 4; mt++)
#pragma unroll
                for (int nt = 0; nt < 8; nt++) {
                    uint32_t* bfh = &bh[nt >> 1][(nt & 1) * 2];
                    uint32_t* bfl = &bl[nt >> 1][(nt & 1) * 2];
                    MMA16816(acc[mt][nt], ah[mt], bfh);
                    MMA16816(acc[mt][nt], ah[mt], bfl);
                    MMA16816(acc[mt][nt], al[mt], bfh);
                }
        }
        FENCE_ASYNC();
        MBAR_ARRIVE(empty0 + b * 8);
    }

    // ---- epilogue: threshold + store ----
#pragma unroll
    for (int mt = 0; mt < 4; mt++) {
        int row0 = bm + warpM * 64 + mt * 16 + (lane >> 2);
#pragma unroll
        for (int nt = 0; nt < 8; nt++) {
            int col = bn + warpN * 64 + nt * 8 + (lane & 3) * 2;
            float2 v0, v1;
            v0.x = acc[mt][nt][0] > 1.0f ? 1.0f : 0.0f;
            v0.y = acc[mt][nt][1] > 1.0f ? 1.0f : 0.0f;
            v1.x = acc[mt][nt][2] > 1.0f ? 1.0f : 0.0f;
            v1.y = acc[mt][nt][3] > 1.0f ? 1.0f : 0.0f;
            *(float2*)(out + (size_t)row0 * P_DIM + col) = v0;
            *(float2*)(out + (size_t)(row0 + 8) * P_DIM + col) = v1;
        }
    }
}

// ---------------------------------------------------------------- launch
extern "C" void kernel_launch(void* const* d_in, const int* in_sizes, int n_in,
                              void* d_out, int out_size) {
    const float* u        = (const float*)d_in[0];
    const float* Lambda   = (const float*)d_in[1];
    const float* log_step = (const float*)d_in[2];
    const float* V_re     = (const float*)d_in[3];
    const float* V_im     = (const float*)d_in[4];
    float* out            = (float*)d_out;
    (void)in_sizes; (void)n_in; (void)out_size;

    cudaFuncSetAttribute(gemm_spike_mma,
                         cudaFuncAttributeMaxDynamicSharedMemorySize, GSMEM_TOTAL);

    prep_kernel<<<P_DIM, 256>>>(Lambda, log_step, V_re, V_im);

    local_scan_kernel<<<NCHUNK, 256>>>(u);
    carry_scan_kernel<<<P_DIM, NCHUNK>>>();
    final_scan_kernel<<<NCHUNK, 256>>>(u);

    dim3 grid(P_DIM / GBN, L_DIM / GBM);   // (4, 64)
    gemm_spike_mma<<<grid, 256, GSMEM_TOTAL>>>(out);
}

// round 11
// speedup vs baseline: 1.0858x; 1.0858x over previous
#include <cuda_runtime.h>
#include <cuda_fp16.h>
#include <cstdint>

// ---------------------------------------------------------------- dims
#define L_DIM 16384
#define P_DIM 512
#define NCHUNK 256
#define CLEN (L_DIM / NCHUNK)        // 64
#define KTOT 1024                    // complex concat: [Xr | Xi]
#define NKB (KTOT / 32)              // 32 k-blocks of 32 halves (64B)

// ---------------------------------------------------------------- scratch
__device__ float g_lbr[P_DIM], g_lbi[P_DIM];
__device__ float g_bcr[P_DIM], g_bci[P_DIM];
__device__ double g_Ar[P_DIM], g_Ai[P_DIM];
__device__ float g_cfr[NCHUNK * P_DIM], g_cfi[NCHUNK * P_DIM];
__device__ float g_cir[NCHUNK * P_DIM], g_cii[NCHUNK * P_DIM];
// A = [Xr | Xi] fp16 Dekker split planes, k-block-tiled + pre-swizzled:
//   half index = (kb*L + row)*32 + (c ^ ((row>>1)&3))*8 + pos,  kb=k>>5, c=(k>>3)&3, pos=k&7
__device__ __half g_ah[(size_t)L_DIM * KTOT];
__device__ __half g_al[(size_t)L_DIM * KTOT];
// B = [Vr | -Vi] split planes, same tiling over n: (kb*512 + n)*32 + swz
__device__ __half g_bh[P_DIM * KTOT];
__device__ __half g_bl[P_DIM * KTOT];

// ---------------------------------------------------------------- helpers
__device__ __forceinline__ uint32_t smem_u32(const void* p) {
    uint32_t a;
    asm("{ .reg .u64 t; cvta.to.shared.u64 t, %1; cvt.u32.u64 %0, t; }" : "=r"(a) : "l"(p));
    return a;
}
__device__ __forceinline__ void split_h(float x, __half& h, __half& l) {
    h = __float2half_rn(x);
    float r = x - __half2float(h);
    l = __float2half_rn(r);
}
__device__ __forceinline__ void ldsm4(uint32_t* r, uint32_t addr) {
    asm volatile("ldmatrix.sync.aligned.m8n8.x4.shared.b16 {%0,%1,%2,%3}, [%4];"
                 : "=r"(r[0]), "=r"(r[1]), "=r"(r[2]), "=r"(r[3]) : "r"(addr));
}
#define MMA16816(c, a, b)                                                        \
    asm volatile("mma.sync.aligned.m16n8k16.row.col.f32.f16.f16.f32 "            \
                 "{%0,%1,%2,%3}, {%4,%5,%6,%7}, {%8,%9}, {%0,%1,%2,%3};"         \
                 : "+f"((c)[0]), "+f"((c)[1]), "+f"((c)[2]), "+f"((c)[3])        \
                 : "r"((a)[0]), "r"((a)[1]), "r"((a)[2]), "r"((a)[3]),           \
                   "r"((b)[0]), "r"((b)[1]))

#define MBAR_INIT(a, n) asm volatile("mbarrier.init.shared.b64 [%0], %1;" :: "r"(a), "r"(n) : "memory")
#define MBAR_ARRIVE(a)  asm volatile("mbarrier.arrive.shared.b64 _, [%0];" :: "r"(a) : "memory")
#define MBAR_EXPECT_TX(a, n) asm volatile("mbarrier.arrive.expect_tx.shared.b64 _, [%0], %1;" :: "r"(a), "r"(n) : "memory")
#define MBAR_WAIT(a, ph) do {                                                      \
    uint32_t _m = (a); uint32_t _p = (ph); uint32_t _d;                            \
    asm volatile("{ .reg .pred p; mbarrier.try_wait.parity.acquire.cta.shared::cta.b64 p, [%1], %2; selp.b32 %0,1,0,p; }" \
        : "=r"(_d) : "r"(_m), "r"(_p) : "memory");                                 \
    if (!_d) {                                                                     \
        asm volatile("{ .reg .pred P1; WL_%=: mbarrier.try_wait.parity.acquire.cta.shared::cta.b64 P1, [%0], %1, 0x989680;\n\t" \
            "@P1 bra.uni WD_%=; bra.uni WL_%=; WD_%=: }" :: "r"(_m), "r"(_p) : "memory"); \
    } } while (0)
#define FENCE_ASYNC() asm volatile("fence.proxy.async.shared::cta;" ::: "memory")

__device__ __forceinline__ void bulk_g2s(uint32_t smem_dst, const void* gmem_src,
                                         uint32_t bytes, uint32_t mbar) {
    asm volatile("cp.async.bulk.shared::cluster.global.mbarrier::complete_tx::bytes "
                 "[%0], [%1], %2, [%3];"
                 :: "r"(smem_dst), "l"(gmem_src), "r"(bytes), "r"(mbar) : "memory");
}

// ---------------------------------------------------------------- prep
__global__ void prep_kernel(const float* __restrict__ Lambda,
                            const float* __restrict__ log_step,
                            const float* __restrict__ Vr,
                            const float* __restrict__ Vi) {
    int n = blockIdx.x;
    int nsw = (n >> 1) & 3;
    for (int k = threadIdx.x; k < KTOT; k += blockDim.x) {
        float v = (k < P_DIM) ? Vr[n * P_DIM + k] : -Vi[n * P_DIM + (k - P_DIM)];
        __half h, l; split_h(v, h, l);
        int kb = k >> 5;
        int c = ((k >> 3) & 3) ^ nsw;
        size_t idx = ((size_t)kb * P_DIM + n) * 32 + c * 8 + (k & 7);
        g_bh[idx] = h;
        g_bl[idx] = l;
    }
    if (threadIdx.x == 0) {
        int p = n;
        float lre = -expf(Lambda[2 * p + 0]);
        float lim =  Lambda[2 * p + 1];
        float s   =  expf(log_step[p]);
        float er  =  expf(lre * s);
        float lbr = er * cosf(lim * s);
        float lbi = er * sinf(lim * s);
        g_lbr[p] = lbr; g_lbi[p] = lbi;
        float den = lre * lre + lim * lim;
        float nr = lbr - 1.0f, ni = lbi;
        g_bcr[p] = (nr * lre + ni * lim) / den;
        g_bci[p] = (ni * lre - nr * lim) / den;
        double ar = 1.0, ai = 0.0, br = (double)lbr, bi = (double)lbi;
        int e = CLEN;
        while (e) {
            if (e & 1) { double t = ar * br - ai * bi; ai = ar * bi + ai * br; ar = t; }
            double t2 = br * br - bi * bi; bi = 2.0 * br * bi; br = t2;
            e >>= 1;
        }
        g_Ar[p] = ar; g_Ai[p] = ai;
    }
}

// ---------------------------------------------------------------- scans
// grid NCHUNK, block 256: each thread owns channels p0=2*tid, p0+1 (2x ILP).
__global__ void local_scan_kernel(const float* __restrict__ u) {
    int t = threadIdx.x;
    int c = blockIdx.x;
    int p0 = 2 * t;
    float lr0 = g_lbr[p0],   li0 = g_lbi[p0],   br0 = g_bcr[p0],   bi0 = g_bci[p0];
    float lr1 = g_lbr[p0+1], li1 = g_lbi[p0+1], br1 = g_bcr[p0+1], bi1 = g_bci[p0+1];
    float xr0 = 0.0f, xi0 = 0.0f, xr1 = 0.0f, xi1 = 0.0f;
    const float* up = u + (size_t)(c * CLEN) * P_DIM + p0;
#pragma unroll 4
    for (int i = 0; i < CLEN; i++) {
        float2 uv = *(const float2*)(up + (size_t)i * P_DIM);
        float nr0 = fmaf(lr0, xr0, fmaf(-li0, xi0, br0 * uv.x));
        float ni0 = fmaf(lr0, xi0, fmaf( li0, xr0, bi0 * uv.x));
        float nr1 = fmaf(lr1, xr1, fmaf(-li1, xi1, br1 * uv.y));
        float ni1 = fmaf(lr1, xi1, fmaf( li1, xr1, bi1 * uv.y));
        xr0 = nr0; xi0 = ni0; xr1 = nr1; xi1 = ni1;
    }
    g_cfr[c * P_DIM + p0] = xr0;     g_cfi[c * P_DIM + p0] = xi0;
    g_cfr[c * P_DIM + p0 + 1] = xr1; g_cfi[c * P_DIM + p0 + 1] = xi1;
}

// Shuffle-based log-depth inter-chunk carry scan (double precision).
// Block = 256 threads = NCHUNK chunks for channel p = blockIdx.x.
__global__ void carry_scan_kernel() {
    const int p = blockIdx.x;
    const int c = threadIdx.x;
    const int lane = c & 31;
    const int w = c >> 5;

    double vr = (double)g_cfr[c * P_DIM + p];
    double vi = (double)g_cfi[c * P_DIM + p];
    double qr = g_Ar[p], qi = g_Ai[p];

    double p2r[5], p2i[5];
    int kidx = 0;
#pragma unroll
    for (int s = 1; s < 32; s <<= 1) {
        p2r[kidx] = qr; p2i[kidx] = qi; kidx++;
        double tr = __shfl_up_sync(0xffffffffu, vr, s);
        double ti = __shfl_up_sync(0xffffffffu, vi, s);
        if (lane >= s) {
            vr = fma(qr, tr, fma(-qi, ti, vr));
            vi = fma(qr, ti, fma( qi, tr, vi));
        }
        double nqr = qr * qr - qi * qi;
        qi = 2.0 * qr * qi;
        qr = nqr;
    }

    __shared__ double swr[8], swi[8];
    if (lane == 31) { swr[w] = vr; swi[w] = vi; }
    __syncthreads();

    if (w == 0 && lane < 8) {
        double xr = swr[lane], xi = swi[lane];
        double mr = qr, mi = qi;
#pragma unroll
        for (int s = 1; s < 8; s <<= 1) {
            double tr = __shfl_up_sync(0xffu, xr, s);
            double ti = __shfl_up_sync(0xffu, xi, s);
            if (lane >= s) {
                xr = fma(mr, tr, fma(-mi, ti, xr));
                xi = fma(mr, ti, fma( mi, tr, xi));
            }
            double nmr = mr * mr - mi * mi;
            mi = 2.0 * mr * mi;
            mr = nmr;
        }
        swr[lane] = xr; swi[lane] = xi;
    }
    __syncthreads();

    double er = __shfl_up_sync(0xffffffffu, vr, 1);
    double ei = __shfl_up_sync(0xffffffffu, vi, 1);
    if (lane == 0) { er = 0.0; ei = 0.0; }

    if (w > 0) {
        double plr = 1.0, pli = 0.0;
#pragma unroll
        for (int k = 0; k < 5; k++) {
            if ((lane >> k) & 1) {
                double t = plr * p2r[k] - pli * p2i[k];
                pli = plr * p2i[k] + pli * p2r[k];
                plr = t;
            }
        }
        double Wr = swr[w - 1], Wi = swi[w - 1];
        er = fma(plr, Wr, fma(-pli, Wi, er));
        ei = fma(plr, Wi, fma( pli, Wr, ei));
    }

    g_cir[c * P_DIM + p] = (float)er;
    g_cii[c * P_DIM + p] = (float)ei;
}

// Final scan writing A planes (tiled-swizzled). grid NCHUNK, 2 channels/thread,
// paired half2 stores (adjacent channels share kb/coff, consecutive pos).
__global__ void final_scan_kernel(const float* __restrict__ u) {
    int t = threadIdx.x;
    int c = blockIdx.x;
    int p0 = 2 * t;
    float lr0 = g_lbr[p0],   li0 = g_lbi[p0],   br0 = g_bcr[p0],   bi0 = g_bci[p0];
    float lr1 = g_lbr[p0+1], li1 = g_lbi[p0+1], br1 = g_bcr[p0+1], bi1 = g_bci[p0+1];
    float xr0 = g_cir[c * P_DIM + p0],     xi0 = g_cii[c * P_DIM + p0];
    float xr1 = g_cir[c * P_DIM + p0 + 1], xi1 = g_cii[c * P_DIM + p0 + 1];
    const float* up = u + (size_t)(c * CLEN) * P_DIM + p0;
    const size_t row0 = (size_t)(c * CLEN);
    const int kbr = p0 >> 5;                // Xr k-block
    const int kbi = (P_DIM >> 5) + kbr;     // Xi k-block
    const int coff = (p0 >> 3) & 3;         // same for p0+1 (p0 even)
    const int pos = p0 & 7;                 // even; p0+1 -> pos+1
#pragma unroll 4
    for (int i = 0; i < CLEN; i++) {
        float2 uv = *(const float2*)(up + (size_t)i * P_DIM);
        float nr0 = fmaf(lr0, xr0, fmaf(-li0, xi0, br0 * uv.x));
        float ni0 = fmaf(lr0, xi0, fmaf( li0, xr0, bi0 * uv.x));
        float nr1 = fmaf(lr1, xr1, fmaf(-li1, xi1, br1 * uv.y));
        float ni1 = fmaf(lr1, xi1, fmaf( li1, xr1, bi1 * uv.y));
        xr0 = nr0; xi0 = ni0; xr1 = nr1; xi1 = ni1;

        size_t row = row0 + i;
        int swz = (coff ^ ((int)(row >> 1) & 3)) * 8 + pos;
        size_t idxr = ((size_t)kbr * L_DIM + row) * 32 + swz;
        size_t idxi = ((size_t)kbi * L_DIM + row) * 32 + swz;

        __half h0, l0, h1, l1;
        split_h(xr0, h0, l0);
        split_h(xr1, h1, l1);
        *(__half2*)(g_ah + idxr) = __halves2half2(h0, h1);
        *(__half2*)(g_al + idxr) = __halves2half2(l0, l1);
        split_h(xi0, h0, l0);
        split_h(xi1, h1, l1);
        *(__half2*)(g_ah + idxi) = __halves2half2(h0, h1);
        *(__half2*)(g_al + idxi) = __halves2half2(l0, l1);
    }
}

// ---------------------------------------------------------------- GEMM (mma.sync f16 x3, bulk-DMA pipeline)
// 128x256 CTA tile (M x N), 8 warps 2(M) x 4(N), 64x64 per warp.
// 4-stage mbarrier pipe. N-major tiling halves A-plane DRAM rereads (2x vs 4x).
#define GBM 128
#define GBN 256
#define NS 4
#define NSTOT NKB                         // 32 stages of k32
#define A_PL 8192                         // 128 rows * 64B
#define B_PL 16384                        // 256 rows * 64B
#define STG (2 * A_PL + 2 * B_PL)         // 49152
#define OFF_AH 0
#define OFF_AL A_PL
#define OFF_BH (2 * A_PL)
#define OFF_BL (2 * A_PL + B_PL)
#define BAR_OFF (NS * STG)
#define GSMEM_TOTAL (NS * STG + 128)      // 196736

__global__ __launch_bounds__(256, 1)
void gemm_spike_mma(float* __restrict__ out) {
    extern __shared__ __align__(1024) char smem[];
    const uint32_t sbase = smem_u32(smem);
    const int tid = threadIdx.x;
    const int lane = tid & 31;
    const int wid = tid >> 5;
    const int warpM = wid & 1;            // 2 warps over M (64 rows each)
    const int warpN = wid >> 1;           // 4 warps over N (64 cols each)
    const int bm = blockIdx.y * GBM;
    const int bn = blockIdx.x * GBN;

    const uint32_t full0  = sbase + BAR_OFF;
    const uint32_t empty0 = sbase + BAR_OFF + 32;

    if (tid == 0) {
#pragma unroll
        for (int b = 0; b < NS; b++) {
            MBAR_INIT(full0 + b * 8, 1);
            MBAR_INIT(empty0 + b * 8, 256);
        }
    }
    __syncthreads();

    auto issue = [&](int si) {
        const uint32_t buf = sbase + (uint32_t)(si & (NS - 1)) * STG;
        MBAR_EXPECT_TX(full0 + (si & (NS - 1)) * 8, STG);
        const uint32_t mb = full0 + (si & (NS - 1)) * 8;
        bulk_g2s(buf + OFF_AH, g_ah + ((size_t)si * L_DIM + bm) * 32, A_PL, mb);
        bulk_g2s(buf + OFF_AL, g_al + ((size_t)si * L_DIM + bm) * 32, A_PL, mb);
        bulk_g2s(buf + OFF_BH, g_bh + ((size_t)si * P_DIM + bn) * 32, B_PL, mb);
        bulk_g2s(buf + OFF_BL, g_bl + ((size_t)si * P_DIM + bn) * 32, B_PL, mb);
    };

    if (tid == 0) {
        for (int si = 0; si < NS - 1; si++) issue(si);
    }

    float acc[4][8][4];
#pragma unroll
    for (int i = 0; i < 4; i++)
#pragma unroll
        for (int j = 0; j < 8; j++)
#pragma unroll
            for (int q = 0; q < 4; q++) acc[i][j][q] = 0.0f;

    const int a_r = warpM * 64 + (lane & 15);
    const int a_cbase = (lane >> 4);
    const int b_r = warpN * 64 + (lane & 7) + ((lane >> 4) << 3);
    const int b_cbase = (lane >> 3) & 1;

    for (int s = 0; s < NSTOT; s++) {
        const int b = s & (NS - 1);
        if (tid == 0) {
            int si = s + NS - 1;
            if (si < NSTOT) {
                int bb = si & (NS - 1);
                if (si >= NS) MBAR_WAIT(empty0 + bb * 8, ((si >> 2) - 1) & 1);
                issue(si);
            }
        }
        MBAR_WAIT(full0 + b * 8, (s >> 2) & 1);

        const uint32_t buf = sbase + (uint32_t)b * STG;
        const uint32_t sAh = buf + OFF_AH;
        const uint32_t sAl = buf + OFF_AL;
        const uint32_t sBh = buf + OFF_BH;
        const uint32_t sBl = buf + OFF_BL;

#pragma unroll
        for (int kk = 0; kk < 2; kk++) {
            uint32_t ah[4][4], al[4][4];
#pragma unroll
            for (int mt = 0; mt < 4; mt++) {
                int r = a_r + mt * 16;
                int c = kk * 2 + a_cbase;
                uint32_t off = (uint32_t)(r * 64 + ((c ^ ((r >> 1) & 3)) << 4));
                ldsm4(ah[mt], sAh + off);
                ldsm4(al[mt], sAl + off);
            }
            uint32_t bh[4][4], bl[4][4];
#pragma unroll
            for (int nh = 0; nh < 4; nh++) {
                int r = b_r + nh * 16;
                int c = kk * 2 + b_cbase;
                uint32_t off = (uint32_t)(r * 64 + ((c ^ ((r >> 1) & 3)) << 4));
                ldsm4(bh[nh], sBh + off);
                ldsm4(bl[nh], sBl + off);
            }
#pragma unroll
            for (int mt = 0; mt < 4; mt++)
#pragma unroll
                for (int nt = 0; nt < 8; nt++) {
                    uint32_t* bfh = &bh[nt >> 1][(nt & 1) * 2];
                    uint32_t* bfl = &bl[nt >> 1][(nt & 1) * 2];
                    MMA16816(acc[mt][nt], ah[mt], bfh);
                    MMA16816(acc[mt][nt], ah[mt], bfl);
                    MMA16816(acc[mt][nt], al[mt], bfh);
                }
        }
        FENCE_ASYNC();
        MBAR_ARRIVE(empty0 + b * 8);
    }

    // ---- epilogue: threshold + store ----
#pragma unroll
    for (int mt = 0; mt < 4; mt++) {
        int row0 = bm + warpM * 64 + mt * 16 + (lane >> 2);
#pragma unroll
        for (int nt = 0; nt < 8; nt++) {
            int col = bn + warpN * 64 + nt * 8 + (lane & 3) * 2;
            float2 v0, v1;
            v0.x = acc[mt][nt][0] > 1.0f ? 1.0f : 0.0f;
            v0.y = acc[mt][nt][1] > 1.0f ? 1.0f : 0.0f;
            v1.x = acc[mt][nt][2] > 1.0f ? 1.0f : 0.0f;
            v1.y = acc[mt][nt][3] > 1.0f ? 1.0f : 0.0f;
            *(float2*)(out + (size_t)row0 * P_DIM + col) = v0;
            *(float2*)(out + (size_t)(row0 + 8) * P_DIM + col) = v1;
        }
    }
}

// ---------------------------------------------------------------- launch
extern "C" void kernel_launch(void* const* d_in, const int* in_sizes, int n_in,
                              void* d_out, int out_size) {
    const float* u        = (const float*)d_in[0];
    const float* Lambda   = (const float*)d_in[1];
    const float* log_step = (const float*)d_in[2];
    const float* V_re     = (const float*)d_in[3];
    const float* V_im     = (const float*)d_in[4];
    float* out            = (float*)d_out;
    (void)in_sizes; (void)n_in; (void)out_size;

    cudaFuncSetAttribute(gemm_spike_mma,
                         cudaFuncAttributeMaxDynamicSharedMemorySize, GSMEM_TOTAL);

    prep_kernel<<<P_DIM, 256>>>(Lambda, log_step, V_re, V_im);

    local_scan_kernel<<<NCHUNK, 256>>>(u);
    carry_scan_kernel<<<P_DIM, NCHUNK>>>();
    final_scan_kernel<<<NCHUNK, 256>>>(u);

    dim3 grid(P_DIM / GBN, L_DIM / GBM);   // (2, 128)
    gemm_spike_mma<<<grid, 256, GSMEM_TOTAL>>>(out);
}